// round 16
// baseline (speedup 1.0000x reference)
#include <cuda_runtime.h>
#include <cuda_fp16.h>
#include <cstdint>

// LSTMAnomalyDetector: B=4096, T=512, I=3, H=64 (PyTorch gate order i,f,g,o)
//
// Round-16: HMMA with TWO independent barrier domains per CTA.
// grid=128 CTAs x 512 threads; each CTA = 2 groups of 8 warps; group g owns
// 16 batch rows (row0 = bid*32 + 16g) with its OWN double-buffered A-tile and
// syncs only via named barrier (1+g). Groups drift out of phase so one group's
// MUFU tail overlaps the other's HMMA burst.
// Per warp: warp = N-set s (units 8s..8s+7), M=16 tile; 4 gate-tiles x 5 K
// = 20 HMMA/step. B=[Whh|Wih|bias] in registers. Nonlinearities in-register,
// c fp32 in regs, h written back fp16. Decode SIMT by 48 threads per group.

#define B_    4096
#define T_    512
#define NT    512
#define GR    16          // rows per group
#define PH    88          // A-tile pitch in halfs (176B)
#define PHB   176

__device__ __forceinline__ float tanhfast(float v) {
    float y; asm("tanh.approx.f32 %0, %1;" : "=f"(y) : "f"(v)); return y;
}
__device__ __forceinline__ float sigf(float v) {
    return fmaf(0.5f, tanhfast(0.5f * v), 0.5f);
}
__device__ __forceinline__ uint32_t smem_u32(const void* p) {
    uint32_t a;
    asm("{ .reg .u64 t; cvta.to.shared.u64 t, %1; cvt.u32.u64 %0, t; }" : "=r"(a) : "l"(p));
    return a;
}
__device__ __forceinline__ uint32_t h2u(float a, float b) {
    __half2 h = __floats2half2_rn(a, b);
    return *(uint32_t*)&h;
}
__device__ __forceinline__ void ldm4(uint32_t* r, uint32_t addr) {
    asm volatile("ldmatrix.sync.aligned.m8n8.x4.shared.b16 {%0,%1,%2,%3}, [%4];"
                 : "=r"(r[0]), "=r"(r[1]), "=r"(r[2]), "=r"(r[3]) : "r"(addr));
}
__device__ __forceinline__ void mma_z(float* d, const uint32_t* a, const uint32_t* b) {
    const float z = 0.0f;
    asm volatile("mma.sync.aligned.m16n8k16.row.col.f32.f16.f16.f32 "
                 "{%0,%1,%2,%3}, {%4,%5,%6,%7}, {%8,%9}, {%10,%10,%10,%10};"
                 : "=f"(d[0]), "=f"(d[1]), "=f"(d[2]), "=f"(d[3])
                 : "r"(a[0]), "r"(a[1]), "r"(a[2]), "r"(a[3]),
                   "r"(b[0]), "r"(b[1]), "f"(z));
}
__device__ __forceinline__ void mma_acc(float* d, const uint32_t* a, const uint32_t* b) {
    asm volatile("mma.sync.aligned.m16n8k16.row.col.f32.f16.f16.f32 "
                 "{%0,%1,%2,%3}, {%4,%5,%6,%7}, {%8,%9}, {%0,%1,%2,%3};"
                 : "+f"(d[0]), "+f"(d[1]), "+f"(d[2]), "+f"(d[3])
                 : "r"(a[0]), "r"(a[1]), "r"(a[2]), "r"(a[3]),
                   "r"(b[0]), "r"(b[1]));
}
__device__ __forceinline__ void gbar(int id) {   // group barrier, 8 warps
    asm volatile("bar.sync %0, 256;" :: "r"(id) : "memory");
}

__global__ void __launch_bounds__(NT)
lstm_hmma_kernel(const float* __restrict__ x,      // [B, T, 3]
                 const float* __restrict__ Wih,    // [256, 3]
                 const float* __restrict__ Whh,    // [256, 64]
                 const float* __restrict__ bih,    // [256]
                 const float* __restrict__ bhh,    // [256]
                 const float* __restrict__ Wdec,   // [3, 64]
                 const float* __restrict__ bdec,   // [3]
                 float* __restrict__ out)          // [B, T, 3]
{
    // per group g, per buffer: [16 rows][PH]: cols 0-63 h, 64-66 x, 67=1, 68+ pad
    __shared__ __align__(16) __half At[2][2][GR * PH];
    __shared__ float wdecs[3 * 64];

    const int tid  = threadIdx.x;
    const int wid  = tid >> 5;
    const int lane = tid & 31;
    const int g    = wid >> 3;        // group 0/1
    const int s    = wid & 7;         // N set: units 8s..8s+7 of each gate
    const int ltid = tid & 255;       // id within group
    const int row0 = blockIdx.x * 32 + g * GR;
    const int bar  = 1 + g;

    // ---- setup -----------------------------------------------------------
    for (int i = tid; i < 2 * 2 * GR * (PH / 2); i += NT) ((uint32_t*)At)[i] = 0u;
    for (int i = tid; i < 192; i += NT) wdecs[i] = Wdec[i];
    __syncthreads();
    if (ltid < 48) {    // x(0) -> buffer 0 of my group
        const int o = ltid >> 4, r = ltid & 15;
        At[g][0][r * PH + 64 + o] =
            __float2half_rn(x[((size_t)(row0 + r) * T_) * 3 + o]);
    }
    if (ltid < GR) {    // constant-1 column in BOTH buffers
        At[g][0][ltid * PH + 67] = __float2half_rn(1.0f);
        At[g][1][ltid * PH + 67] = __float2half_rn(1.0f);
    }

    // B fragments in registers: [gate][ktile][2]; col = 64*gate + 8s + lane/4
    uint32_t bF[4][5][2];
#pragma unroll
    for (int gt_ = 0; gt_ < 4; gt_++) {
        const int col = 64 * gt_ + 8 * s + (lane >> 2);
        const int kq  = (lane & 3) * 2;
#pragma unroll
        for (int kt = 0; kt < 4; kt++) {
            const int k0 = 16 * kt + kq;
            bF[gt_][kt][0] = h2u(Whh[col * 64 + k0],     Whh[col * 64 + k0 + 1]);
            bF[gt_][kt][1] = h2u(Whh[col * 64 + k0 + 8], Whh[col * 64 + k0 + 9]);
        }
        float va = 0.f, vb = 0.f;   // ktile 4: rows 64-66 = Wih, 67 = bias, rest 0
        if (kq == 0)      { va = Wih[col * 3 + 0]; vb = Wih[col * 3 + 1]; }
        else if (kq == 2) { va = Wih[col * 3 + 2]; vb = bih[col] + bhh[col]; }
        bF[gt_][4][0] = h2u(va, vb);
        bF[gt_][4][1] = 0u;
    }

    float c_[4];
#pragma unroll
    for (int j = 0; j < 4; j++) c_[j] = 0.0f;

    float bdv = 0.0f;
    if (ltid < 48) bdv = bdec[ltid >> 4];

    // ldmatrix lane addresses (m16 tile over the group's 16 rows)
    const uint32_t arow = (uint32_t)(((lane & 7) + ((lane >> 3) & 1) * 8) * PHB)
                        + (uint32_t)(((lane >> 4) & 1) * 16);
    const uint32_t ab0 = smem_u32(&At[g][0][0]) + arow;
    const uint32_t ab1 = smem_u32(&At[g][1][0]) + arow;

    // nonlinearity / writeback coordinates
    const int ra = lane >> 2;                 // row a (row b = ra+8)
    const int u0 = 8 * s + (lane & 3) * 2;    // unit pair base

    __syncthreads();

    // ---- timestep loop -----------------------------------------------------
    for (int t = 0; t < T_; t++) {
        const int cur = t & 1, nxt = cur ^ 1;
        const uint32_t abase = cur ? ab1 : ab0;

        // phase 1: A fragments; decode h(t-1); prefetch x(t+1)
        uint32_t aF[5][4];
#pragma unroll
        for (int kt = 0; kt < 5; kt++) ldm4(aF[kt], abase + 32u * kt);

        float xr = 0.0f;
        if (ltid < 48) {
            const int o = ltid >> 4, r = ltid & 15;
            if (t + 1 < T_)
                xr = x[((size_t)(row0 + r) * T_ + (t + 1)) * 3 + o];
            if (t > 0) {
                const uint32_t* hrow = (const uint32_t*)(&At[g][cur][r * PH]);
                float dsum = bdv;
#pragma unroll 8
                for (int k2 = 0; k2 < 32; k2++) {
                    const float2 hv = __half22float2(*(const __half2*)&hrow[k2]);
                    dsum = fmaf(hv.x, wdecs[o * 64 + 2 * k2],     dsum);
                    dsum = fmaf(hv.y, wdecs[o * 64 + 2 * k2 + 1], dsum);
                }
                out[((size_t)(row0 + r) * T_ + (t - 1)) * 3 + o] = dsum;
            }
        }

        // phase 2: HMMA (4 independent 5-chains)
        float acc[4][4];
#pragma unroll
        for (int gt_ = 0; gt_ < 4; gt_++) {
            mma_z(acc[gt_], aF[0], bF[gt_][0]);
#pragma unroll
            for (int kt = 1; kt < 5; kt++)
                mma_acc(acc[gt_], aF[kt], bF[gt_][kt]);
        }

        // phase 3: nonlinearities + h writeback into buf[nxt]
        // acc[gate][j]: j=0 (ra,u0) j=1 (ra,u0+1) j=2 (ra+8,u0) j=3 (ra+8,u0+1)
        float h_[4];
#pragma unroll
        for (int j = 0; j < 4; j++) {
            const float ig = sigf(acc[0][j]);
            const float fg = sigf(acc[1][j]);
            const float gt = tanhfast(acc[2][j]);
            const float og = sigf(acc[3][j]);
            const float cn = fmaf(fg, c_[j], ig * gt);
            c_[j] = cn;
            h_[j] = og * tanhfast(cn);
        }
        *(__half2*)&At[g][nxt][ra * PH + u0]       = __floats2half2_rn(h_[0], h_[1]);
        *(__half2*)&At[g][nxt][(ra + 8) * PH + u0] = __floats2half2_rn(h_[2], h_[3]);

        // stage x(t+1) into buf[nxt]
        if (ltid < 48 && (t + 1) < T_)
            At[g][nxt][(ltid & 15) * PH + 64 + (ltid >> 4)] = __float2half_rn(xr);

        gbar(bar);   // group-local barrier: buf[nxt] complete for step t+1
    }

    // epilogue: decode h(T-1) (written into buffer (T_)&1 = 0)
    if (ltid < 48) {
        const int o = ltid >> 4, r = ltid & 15;
        const uint32_t* hrow = (const uint32_t*)(&At[g][0][r * PH]);
        float dsum = bdv;
#pragma unroll 8
        for (int k2 = 0; k2 < 32; k2++) {
            const float2 hv = __half22float2(*(const __half2*)&hrow[k2]);
            dsum = fmaf(hv.x, wdecs[o * 64 + 2 * k2],     dsum);
            dsum = fmaf(hv.y, wdecs[o * 64 + 2 * k2 + 1], dsum);
        }
        out[((size_t)(row0 + r) * T_ + (T_ - 1)) * 3 + o] = dsum;
    }
}

extern "C" void kernel_launch(void* const* d_in, const int* in_sizes, int n_in,
                              void* d_out, int out_size) {
    const float* x    = (const float*)d_in[0];
    const float* Wih  = (const float*)d_in[1];
    const float* Whh  = (const float*)d_in[2];
    const float* bih  = (const float*)d_in[3];
    const float* bhh  = (const float*)d_in[4];
    const float* Wdec = (const float*)d_in[5];
    const float* bdec = (const float*)d_in[6];
    float* out = (float*)d_out;

    lstm_hmma_kernel<<<B_ / 32, NT>>>(x, Wih, Whh, bih, bhh, Wdec, bdec, out);
}

// round 17
// speedup vs baseline: 1.0829x; 1.0829x over previous
#include <cuda_runtime.h>
#include <cuda_fp16.h>
#include <cstdint>

// LSTMAnomalyDetector: B=4096, T=512, I=3, H=64 (PyTorch gate order i,f,g,o)
//
// Round-17: HMMA dual-pipeline warps. grid=128 CTAs x 256 threads, 32 rows/CTA
// persistent. 8 warps; warp = N-set s (units 8s..8s+7 of each gate) and owns
// BOTH M-tiles (rows 0-15, 16-31) as two independent pipelines interleaved in
// one instruction stream: ldm0+ldm1 -> MMA0 -> MMA1 -> MUFU0 (MMA1 drains
// underneath) -> MUFU1. Guaranteed intra-warp overlap of the serial chains.
// B=[Whh|Wih|bias] in registers (40). A=[h|x|1] fp16 double-buffered smem
// tile, ONE barrier/step. c fp32 in regs. Decode SIMT by threads<96 in phase 1.

#define B_    4096
#define T_    512
#define RT    32          // rows per CTA
#define NT    256
#define PH    88          // A-tile pitch in halfs (176B)
#define PHB   176

__device__ __forceinline__ float tanhfast(float v) {
    float y; asm("tanh.approx.f32 %0, %1;" : "=f"(y) : "f"(v)); return y;
}
__device__ __forceinline__ float sigf(float v) {
    return fmaf(0.5f, tanhfast(0.5f * v), 0.5f);
}
__device__ __forceinline__ uint32_t smem_u32(const void* p) {
    uint32_t a;
    asm("{ .reg .u64 t; cvta.to.shared.u64 t, %1; cvt.u32.u64 %0, t; }" : "=r"(a) : "l"(p));
    return a;
}
__device__ __forceinline__ uint32_t h2u(float a, float b) {
    __half2 h = __floats2half2_rn(a, b);
    return *(uint32_t*)&h;
}
__device__ __forceinline__ void ldm4(uint32_t* r, uint32_t addr) {
    asm volatile("ldmatrix.sync.aligned.m8n8.x4.shared.b16 {%0,%1,%2,%3}, [%4];"
                 : "=r"(r[0]), "=r"(r[1]), "=r"(r[2]), "=r"(r[3]) : "r"(addr));
}
__device__ __forceinline__ void mma_z(float* d, const uint32_t* a, const uint32_t* b) {
    const float z = 0.0f;
    asm volatile("mma.sync.aligned.m16n8k16.row.col.f32.f16.f16.f32 "
                 "{%0,%1,%2,%3}, {%4,%5,%6,%7}, {%8,%9}, {%10,%10,%10,%10};"
                 : "=f"(d[0]), "=f"(d[1]), "=f"(d[2]), "=f"(d[3])
                 : "r"(a[0]), "r"(a[1]), "r"(a[2]), "r"(a[3]),
                   "r"(b[0]), "r"(b[1]), "f"(z));
}
__device__ __forceinline__ void mma_acc(float* d, const uint32_t* a, const uint32_t* b) {
    asm volatile("mma.sync.aligned.m16n8k16.row.col.f32.f16.f16.f32 "
                 "{%0,%1,%2,%3}, {%4,%5,%6,%7}, {%8,%9}, {%0,%1,%2,%3};"
                 : "+f"(d[0]), "+f"(d[1]), "+f"(d[2]), "+f"(d[3])
                 : "r"(a[0]), "r"(a[1]), "r"(a[2]), "r"(a[3]),
                   "r"(b[0]), "r"(b[1]));
}

__global__ void __launch_bounds__(NT)
lstm_hmma_kernel(const float* __restrict__ x,      // [B, T, 3]
                 const float* __restrict__ Wih,    // [256, 3]
                 const float* __restrict__ Whh,    // [256, 64]
                 const float* __restrict__ bih,    // [256]
                 const float* __restrict__ bhh,    // [256]
                 const float* __restrict__ Wdec,   // [3, 64]
                 const float* __restrict__ bdec,   // [3]
                 float* __restrict__ out)          // [B, T, 3]
{
    __shared__ __align__(16) __half At[2][RT * PH];  // [buf][row][col]: 0-63 h, 64-66 x, 67=1
    __shared__ float wdecs[3 * 64];

    const int tid  = threadIdx.x;
    const int wid  = tid >> 5;
    const int lane = tid & 31;
    const int row0 = blockIdx.x * RT;
    const int s    = wid;          // N set: units 8s..8s+7 of each gate

    // ---- setup -----------------------------------------------------------
    for (int i = tid; i < 2 * RT * (PH / 2); i += NT) ((uint32_t*)At)[i] = 0u;
    for (int i = tid; i < 192; i += NT) wdecs[i] = Wdec[i];
    __syncthreads();
    if (tid < 96) {   // x(0) -> buffer 0
        const int o = tid >> 5, r = tid & 31;
        At[0][r * PH + 64 + o] = __float2half_rn(x[((size_t)(row0 + r) * T_) * 3 + o]);
    }
    if (tid < RT) {   // constant-1 column in BOTH buffers
        At[0][tid * PH + 67] = __float2half_rn(1.0f);
        At[1][tid * PH + 67] = __float2half_rn(1.0f);
    }

    // B fragments in registers: [gate][ktile][2]; col = 64g + 8s + lane/4
    uint32_t bF[4][5][2];
#pragma unroll
    for (int g = 0; g < 4; g++) {
        const int col = 64 * g + 8 * s + (lane >> 2);
        const int kq  = (lane & 3) * 2;
#pragma unroll
        for (int kt = 0; kt < 4; kt++) {
            const int k0 = 16 * kt + kq;
            bF[g][kt][0] = h2u(Whh[col * 64 + k0],     Whh[col * 64 + k0 + 1]);
            bF[g][kt][1] = h2u(Whh[col * 64 + k0 + 8], Whh[col * 64 + k0 + 9]);
        }
        float va = 0.f, vb = 0.f;   // ktile 4: rows 64-66 = Wih, 67 = bias, rest 0
        if (kq == 0)      { va = Wih[col * 3 + 0]; vb = Wih[col * 3 + 1]; }
        else if (kq == 2) { va = Wih[col * 3 + 2]; vb = bih[col] + bhh[col]; }
        bF[g][4][0] = h2u(va, vb);
        bF[g][4][1] = 0u;
    }

    float c_[2][4];                  // [mtile][j]
#pragma unroll
    for (int p = 0; p < 2; p++)
#pragma unroll
        for (int j = 0; j < 4; j++) c_[p][j] = 0.0f;

    float bdv = 0.0f;
    if (tid < 96) bdv = bdec[tid >> 5];

    // ldmatrix lane addresses per mtile, per buffer (ktile via +32B)
    const uint32_t alane = (uint32_t)(((lane & 7) + ((lane >> 3) & 1) * 8) * PHB)
                         + (uint32_t)(((lane >> 4) & 1) * 16);
    uint32_t ab[2][2];
#pragma unroll
    for (int p = 0; p < 2; p++) {
        ab[0][p] = smem_u32(&At[0][0]) + alane + (uint32_t)(16 * p * PHB);
        ab[1][p] = smem_u32(&At[1][0]) + alane + (uint32_t)(16 * p * PHB);
    }

    const int rj = lane >> 2;                 // row within tile (rows rj, rj+8)
    const int u0 = 8 * s + (lane & 3) * 2;    // unit pair base

    __syncthreads();

    // ---- timestep loop -----------------------------------------------------
    for (int t = 0; t < T_; t++) {
        const int cur = t & 1, nxt = cur ^ 1;

        // phase 1: A fragments for BOTH mtiles; decode h(t-1); prefetch x(t+1)
        uint32_t aF0[5][4], aF1[5][4];
#pragma unroll
        for (int kt = 0; kt < 5; kt++) ldm4(aF0[kt], ab[cur][0] + 32u * kt);
#pragma unroll
        for (int kt = 0; kt < 5; kt++) ldm4(aF1[kt], ab[cur][1] + 32u * kt);

        float xr = 0.0f;
        if (tid < 96) {
            const int o = tid >> 5, r = tid & 31;
            if (t + 1 < T_)
                xr = x[((size_t)(row0 + r) * T_ + (t + 1)) * 3 + o];
            if (t > 0) {
                const uint32_t* hrow = (const uint32_t*)(&At[cur][r * PH]);
                float dsum = bdv;
#pragma unroll 8
                for (int k2 = 0; k2 < 32; k2++) {
                    const float2 hv = __half22float2(*(const __half2*)&hrow[k2]);
                    dsum = fmaf(hv.x, wdecs[o * 64 + 2 * k2],     dsum);
                    dsum = fmaf(hv.y, wdecs[o * 64 + 2 * k2 + 1], dsum);
                }
                out[((size_t)(row0 + r) * T_ + (t - 1)) * 3 + o] = dsum;
            }
        }

        // phase 2: HMMA, pipeline 0 then pipeline 1 (8 independent 5-chains)
        float acc0[4][4], acc1[4][4];
#pragma unroll
        for (int g = 0; g < 4; g++) {
            mma_z(acc0[g], aF0[0], bF[g][0]);
#pragma unroll
            for (int kt = 1; kt < 5; kt++) mma_acc(acc0[g], aF0[kt], bF[g][kt]);
        }
#pragma unroll
        for (int g = 0; g < 4; g++) {
            mma_z(acc1[g], aF1[0], bF[g][0]);
#pragma unroll
            for (int kt = 1; kt < 5; kt++) mma_acc(acc1[g], aF1[kt], bF[g][kt]);
        }

        // phase 3a: MUFU + writeback for pipeline 0 (pipeline 1 MMA drains below)
        {
            float h_[4];
#pragma unroll
            for (int j = 0; j < 4; j++) {
                const float ig = sigf(acc0[0][j]);
                const float fg = sigf(acc0[1][j]);
                const float gt = tanhfast(acc0[2][j]);
                const float og = sigf(acc0[3][j]);
                const float cn = fmaf(fg, c_[0][j], ig * gt);
                c_[0][j] = cn;
                h_[j] = og * tanhfast(cn);
            }
            *(__half2*)&At[nxt][rj * PH + u0]       = __floats2half2_rn(h_[0], h_[1]);
            *(__half2*)&At[nxt][(rj + 8) * PH + u0] = __floats2half2_rn(h_[2], h_[3]);
        }
        // phase 3b: MUFU + writeback for pipeline 1
        {
            float h_[4];
#pragma unroll
            for (int j = 0; j < 4; j++) {
                const float ig = sigf(acc1[0][j]);
                const float fg = sigf(acc1[1][j]);
                const float gt = tanhfast(acc1[2][j]);
                const float og = sigf(acc1[3][j]);
                const float cn = fmaf(fg, c_[1][j], ig * gt);
                c_[1][j] = cn;
                h_[j] = og * tanhfast(cn);
            }
            *(__half2*)&At[nxt][(16 + rj) * PH + u0]     = __floats2half2_rn(h_[0], h_[1]);
            *(__half2*)&At[nxt][(16 + rj + 8) * PH + u0] = __floats2half2_rn(h_[2], h_[3]);
        }

        // stage x(t+1) into buf[nxt]
        if (tid < 96 && (t + 1) < T_)
            At[nxt][(tid & 31) * PH + 64 + (tid >> 5)] = __float2half_rn(xr);

        __syncthreads();   // single barrier: buf[nxt] complete for step t+1
    }

    // epilogue: decode h(T-1) (written into buffer (T_)&1 = 0)
    if (tid < 96) {
        const int o = tid >> 5, r = tid & 31;
        const uint32_t* hrow = (const uint32_t*)(&At[0][r * PH]);
        float dsum = bdv;
#pragma unroll 8
        for (int k2 = 0; k2 < 32; k2++) {
            const float2 hv = __half22float2(*(const __half2*)&hrow[k2]);
            dsum = fmaf(hv.x, wdecs[o * 64 + 2 * k2],     dsum);
            dsum = fmaf(hv.y, wdecs[o * 64 + 2 * k2 + 1], dsum);
        }
        out[((size_t)(row0 + r) * T_ + (T_ - 1)) * 3 + o] = dsum;
    }
}

extern "C" void kernel_launch(void* const* d_in, const int* in_sizes, int n_in,
                              void* d_out, int out_size) {
    const float* x    = (const float*)d_in[0];
    const float* Wih  = (const float*)d_in[1];
    const float* Whh  = (const float*)d_in[2];
    const float* bih  = (const float*)d_in[3];
    const float* bhh  = (const float*)d_in[4];
    const float* Wdec = (const float*)d_in[5];
    const float* bdec = (const float*)d_in[6];
    float* out = (float*)d_out;

    lstm_hmma_kernel<<<B_ / RT, NT>>>(x, Wih, Whh, bih, bhh, Wdec, bdec, out);
}